// round 16
// baseline (speedup 1.0000x reference)
#include <cuda_runtime.h>

#define BATCH   8192
#define KDIM    256
#define EPSF    1e-10f

// Packed fp32x2 ops (Blackwell): only reachable via PTX.
#define FMA_F32X2(d, a, b, c) \
    asm("fma.rn.f32x2 %0, %1, %2, %3;" : "=l"(d) : "l"(a), "l"(b), "l"(c))
#define MUL_F32X2(d, a, b) \
    asm("mul.rn.f32x2 %0, %1, %2;" : "=l"(d) : "l"(a), "l"(b))
#define UNPACK_F32X2(lo, hi, in) do {                                   \
    unsigned _ulo, _uhi;                                                \
    asm("mov.b64 {%0, %1}, %2;" : "=r"(_ulo), "=r"(_uhi) : "l"(in));    \
    lo = __uint_as_float(_ulo); hi = __uint_as_float(_uhi);             \
} while (0)

// Scratch, element-major [BATCH][96]:
// 0..63  -> M8[i][j] = dot(row i,   row 8+j)   (o = i*8+j)
// 64..79 -> ML[i][j] = dot(row i,   row 4+j)
// 80..95 -> MR[i][j] = dot(row 8+i, row 12+j)
__device__ float g_scratch[BATCH * 96];

// ---------------------------------------------------------------------------
// Kernel 1: cross-Gram blocks (R7/R13 proven-best form). One CTA/element,
// direct LDG.128, f32x2 FMAs, scalar 31-shfl multi-value tree.
// boff = element offset of this launch (batch split across 2 launches so the
// harness's fixed "-s 5 -c 1" ncu capture lands on a gram launch).
// ---------------------------------------------------------------------------
__global__ __launch_bounds__(128)
void gram_kernel(const float* __restrict__ sites, int boff) {
    const int b    = blockIdx.x + boff;
    const int tid  = threadIdx.x;
    const int warp = tid >> 5;
    const int lane = tid & 31;

    // Row r = 256 floats = 64 x 16B. Lane owns chunks (lane) and (lane+32).
    const ulonglong2* S2 = (const ulonglong2*)(sites + (size_t)b * (16 * KDIM));

    if (warp < 2) {
        // M8 rows i = warp*4..warp*4+3 vs rows 8..15 -> 32 outputs
        ulonglong2 Ar[4][2];
        #pragma unroll
        for (int a = 0; a < 4; a++) {
            Ar[a][0] = S2[(warp * 4 + a) * 64 + lane];
            Ar[a][1] = S2[(warp * 4 + a) * 64 + lane + 32];
        }
        float v[32];
        #pragma unroll
        for (int j = 0; j < 8; j++) {
            ulonglong2 B0 = S2[(8 + j) * 64 + lane];
            ulonglong2 B1 = S2[(8 + j) * 64 + lane + 32];
            #pragma unroll
            for (int a = 0; a < 4; a++) {
                unsigned long long d;
                MUL_F32X2(d, Ar[a][0].x, B0.x);
                FMA_F32X2(d, Ar[a][0].y, B0.y, d);
                FMA_F32X2(d, Ar[a][1].x, B1.x, d);
                FMA_F32X2(d, Ar[a][1].y, B1.y, d);
                float lo, hi; UNPACK_F32X2(lo, hi, d);
                v[a * 8 + j] = lo + hi;
            }
        }
        // Multi-value tree reduce: lane l ends with output l in v[0].
        #pragma unroll
        for (int stride = 16; stride >= 1; stride >>= 1) {
            #pragma unroll
            for (int j = 0; j < stride; j++) {
                float send = (lane & stride) ? v[j] : v[j + stride];
                float recv = __shfl_xor_sync(0xffffffffu, send, stride);
                v[j] = ((lane & stride) ? v[j + stride] : v[j]) + recv;
            }
        }
        g_scratch[b * 96 + warp * 32 + lane] = v[0];
    } else {
        // warp2: ML (rows 0-3 x 4-7); warp3: MR (rows 8-11 x 12-15) -> 16 outputs
        const int ra   = (warp == 2) ? 0 : 8;
        const int base = (warp == 2) ? 64 : 80;
        ulonglong2 Ar[4][2];
        #pragma unroll
        for (int a = 0; a < 4; a++) {
            Ar[a][0] = S2[(ra + a) * 64 + lane];
            Ar[a][1] = S2[(ra + a) * 64 + lane + 32];
        }
        float v[16];
        #pragma unroll
        for (int j = 0; j < 4; j++) {
            ulonglong2 B0 = S2[(ra + 4 + j) * 64 + lane];
            ulonglong2 B1 = S2[(ra + 4 + j) * 64 + lane + 32];
            #pragma unroll
            for (int a = 0; a < 4; a++) {
                unsigned long long d;
                MUL_F32X2(d, Ar[a][0].x, B0.x);
                FMA_F32X2(d, Ar[a][0].y, B0.y, d);
                FMA_F32X2(d, Ar[a][1].x, B1.x, d);
                FMA_F32X2(d, Ar[a][1].y, B1.y, d);
                float lo, hi; UNPACK_F32X2(lo, hi, d);
                v[a * 4 + j] = lo + hi;
            }
        }
        #pragma unroll
        for (int j = 0; j < 16; j++) v[j] += __shfl_xor_sync(0xffffffffu, v[j], 16);
        #pragma unroll
        for (int stride = 8; stride >= 1; stride >>= 1) {
            #pragma unroll
            for (int j = 0; j < stride; j++) {
                float send = (lane & stride) ? v[j] : v[j + stride];
                float recv = __shfl_xor_sync(0xffffffffu, send, stride);
                v[j] = ((lane & stride) ? v[j + stride] : v[j]) + recv;
            }
        }
        if (lane < 16) g_scratch[b * 96 + base + lane] = v[0];
    }
}

// ---------------------------------------------------------------------------
// Kernel 2: 8 lanes per element (one column per lane, one-sided Jacobi),
// incremental column norms, merged 8x8/4x4 sweeps. Block=32 (R15 best).
// ---------------------------------------------------------------------------
#define ROUND8(r) do {                                                        \
    const int partner = prt8[r];                                              \
    float bc[8];                                                              \
    _Pragma("unroll")                                                         \
    for (int k = 0; k < 8; k++) bc[k] = __shfl_sync(FULL, a[k], partner, 8);  \
    float bn = __shfl_sync(FULL, n8, partner, 8);                             \
    float g0 = 0.f, g1 = 0.f;                                                 \
    _Pragma("unroll")                                                         \
    for (int k = 0; k < 4; k++) g0 = fmaf(a[k], bc[k], g0);                   \
    _Pragma("unroll")                                                         \
    for (int k = 4; k < 8; k++) g1 = fmaf(a[k], bc[k], g1);                   \
    float ga = g0 + g1;                                                       \
    float d = bn - n8;                                                        \
    float den = fabsf(d) + sqrtf(fmaf(d, d, 4.f * ga * ga));                  \
    float t = (2.f * ga * copysignf(1.f, d)) * __fdividef(1.f, den);          \
    t = (fabsf(ga) > 1e-30f) ? t : 0.f;                                       \
    float c = rsqrtf(fmaf(t, t, 1.f));                                        \
    float s = c * t;                                                          \
    _Pragma("unroll")                                                         \
    for (int k = 0; k < 8; k++) a[k] = fmaf(c, a[k], -s * bc[k]);             \
    n8 = fmaf(c * c, n8, fmaf(s * s, bn, -2.f * c * s * ga));                 \
} while (0)

#define ROUND4(r) do {                                                        \
    const int partner = prt4[r];                                              \
    float bc[4];                                                              \
    _Pragma("unroll")                                                         \
    for (int k = 0; k < 4; k++) bc[k] = __shfl_sync(FULL, m4[k], partner, 4); \
    float bn = __shfl_sync(FULL, n4, partner, 4);                             \
    float g0 = fmaf(m4[0], bc[0], 0.f); g0 = fmaf(m4[1], bc[1], g0);          \
    float g1 = fmaf(m4[2], bc[2], 0.f); g1 = fmaf(m4[3], bc[3], g1);          \
    float ga = g0 + g1;                                                       \
    float d = bn - n4;                                                        \
    float den = fabsf(d) + sqrtf(fmaf(d, d, 4.f * ga * ga));                  \
    float t = (2.f * ga * copysignf(1.f, d)) * __fdividef(1.f, den);          \
    t = (fabsf(ga) > 1e-30f) ? t : 0.f;                                       \
    float c = rsqrtf(fmaf(t, t, 1.f));                                        \
    float s = c * t;                                                          \
    _Pragma("unroll")                                                         \
    for (int k = 0; k < 4; k++) m4[k] = fmaf(c, m4[k], -s * bc[k]);           \
    n4 = fmaf(c * c, n4, fmaf(s * s, bn, -2.f * c * s * ga));                 \
} while (0)

__global__ __launch_bounds__(32)
void jacobi_kernel(float* __restrict__ out, int boff) {
    const unsigned FULL = 0xffffffffu;
    const int tid = threadIdx.x;
    const int j   = tid & 7;                              // my column (8x8)
    const int b   = blockIdx.x * 4 + (tid >> 3) + boff;   // element
    const float* base = g_scratch + b * 96;

    float a[8];
    #pragma unroll
    for (int k = 0; k < 8; k++) a[k] = base[k * 8 + j];

    const int j4  = j & 3;
    const int isR = j >> 2;                        // lanes 0-3 -> ML, 4-7 -> MR
    const float* mb = base + 64 + isR * 16;
    float m4[4];
    #pragma unroll
    for (int k = 0; k < 4; k++) m4[k] = mb[k * 4 + j4];

    int prt8[7];
    #pragma unroll
    for (int r = 0; r < 7; r++)
        prt8[r] = (j == r) ? 7 : ((j == 7) ? r : ((2 * r + 14 - j) % 7));
    int prt4[3];
    #pragma unroll
    for (int r = 0; r < 3; r++)
        prt4[r] = (j4 == r) ? 3 : ((j4 == 3) ? r : ((2 * r + 6 - j4) % 3));

    // Initial norms; thereafter updated incrementally per rotation.
    float n8;
    {
        float n0 = 0.f, n1 = 0.f;
        #pragma unroll
        for (int k = 0; k < 4; k++) n0 = fmaf(a[k], a[k], n0);
        #pragma unroll
        for (int k = 4; k < 8; k++) n1 = fmaf(a[k], a[k], n1);
        n8 = n0 + n1;
    }
    float n4;
    {
        float n0 = fmaf(m4[0], m4[0], 0.f); n0 = fmaf(m4[1], m4[1], n0);
        float n1 = fmaf(m4[2], m4[2], 0.f); n1 = fmaf(m4[3], m4[3], n1);
        n4 = n0 + n1;
    }

    // 3 merged sweeps: 7 rounds of 8x8; rounds 0-2 carry a 4x4 round too.
    #pragma unroll 1
    for (int sw = 0; sw < 3; sw++) {
        #pragma unroll
        for (int r = 0; r < 7; r++) {
            ROUND8(r);
            if (r < 3) ROUND4(r);
        }
    }
    // Final 8x8-only sweep (4 sweeps total for 8x8, 3 for 4x4).
    #pragma unroll
    for (int r = 0; r < 7; r++) ROUND8(r);

    // ---- entropies (norms recomputed exactly) ----
    float sq8 = EPSF;
    #pragma unroll
    for (int k = 0; k < 8; k++) sq8 = fmaf(a[k], a[k], sq8);
    float T8 = sq8;
    #pragma unroll
    for (int m = 4; m >= 1; m >>= 1) T8 += __shfl_xor_sync(FULL, T8, m, 8);
    float p8 = sq8 * __fdividef(1.f, T8);
    float s8 = p8 * __logf(p8 + EPSF);
    #pragma unroll
    for (int m = 4; m >= 1; m >>= 1) s8 += __shfl_xor_sync(FULL, s8, m, 8);

    float sq4 = EPSF;
    #pragma unroll
    for (int k = 0; k < 4; k++) sq4 = fmaf(m4[k], m4[k], sq4);
    float T4 = sq4;
    #pragma unroll
    for (int m = 2; m >= 1; m >>= 1) T4 += __shfl_xor_sync(FULL, T4, m, 4);
    float p4 = sq4 * __fdividef(1.f, T4);
    float s4 = p4 * __logf(p4 + EPSF);
    #pragma unroll
    for (int m = 2; m >= 1; m >>= 1) s4 += __shfl_xor_sync(FULL, s4, m, 4);

    float s4R = __shfl_sync(FULL, s4, 4, 8);   // MR sum from lane 4 of group
    if (j == 0) {
        // phi = S_whole - S_left - S_right = -s8 + s4(L) + s4(R)
        float phi = -s8 + s4 + s4R;
        out[b] = phi > 0.f ? phi : 0.f;
    }
}

extern "C" void kernel_launch(void* const* d_in, const int* in_sizes, int n_in,
                              void* d_out, int out_size) {
    const float* sites = (const float*)d_in[0];
    float* out = (float*)d_out;
    const int H = BATCH / 2;
    // Two half-batch launches per kernel: 4 launches/replay puts the
    // harness's fixed "-s 5 -c 1" ncu capture on a GRAM launch (index 5).
    gram_kernel<<<H, 128>>>(sites, 0);
    gram_kernel<<<H, 128>>>(sites, H);
    jacobi_kernel<<<H / 4, 32>>>(out, 0);
    jacobi_kernel<<<H / 4, 32>>>(out, H);
}

// round 17
// speedup vs baseline: 1.1293x; 1.1293x over previous
#include <cuda_runtime.h>
#include <cstdint>

#define BATCH   8192
#define KDIM    256
#define EPSF    1e-10f

// Packed fp32x2 ops (Blackwell): only reachable via PTX.
#define FMA_F32X2(d, a, b, c) \
    asm("fma.rn.f32x2 %0, %1, %2, %3;" : "=l"(d) : "l"(a), "l"(b), "l"(c))
#define MUL_F32X2(d, a, b) \
    asm("mul.rn.f32x2 %0, %1, %2;" : "=l"(d) : "l"(a), "l"(b))
#define UNPACK_F32X2(lo, hi, in) do {                                   \
    unsigned _ulo, _uhi;                                                \
    asm("mov.b64 {%0, %1}, %2;" : "=r"(_ulo), "=r"(_uhi) : "l"(in));    \
    lo = __uint_as_float(_ulo); hi = __uint_as_float(_uhi);             \
} while (0)

__device__ __forceinline__ uint32_t smem_u32(const void* p) {
    uint32_t a;
    asm("{ .reg .u64 t; cvta.to.shared.u64 t, %1; cvt.u32.u64 %0, t; }"
        : "=r"(a) : "l"(p));
    return a;
}

// Scratch, element-major [BATCH][96]:
// 0..63  -> M8[i][j] = dot(row i,   row 8+j)   (o = i*8+j)
// 64..79 -> ML[i][j] = dot(row i,   row 4+j)
// 80..95 -> MR[i][j] = dot(row 8+i, row 12+j)
__device__ float g_scratch[BATCH * 96];

// ---------------------------------------------------------------------------
// Kernel 1: cross-Gram blocks. The 16KB element tile arrives via ONE 1-D TMA
// bulk copy (UBLKCP: no per-lane L1tex wavefronts, no RF traffic); compute is
// the proven R7 shape reading LDS.128 from smem.
// ---------------------------------------------------------------------------
__global__ __launch_bounds__(128)
void gram_kernel(const float* __restrict__ sites) {
    const int b    = blockIdx.x;
    const int tid  = threadIdx.x;
    const int warp = tid >> 5;
    const int lane = tid & 31;

    __shared__ alignas(128) float smS[16 * KDIM];     // 16KB tile
    __shared__ alignas(8) unsigned long long mbar;

    const uint32_t mb = smem_u32(&mbar);
    if (tid == 0) {
        asm volatile("mbarrier.init.shared.b64 [%0], %1;" :: "r"(mb), "r"(1) : "memory");
    }
    __syncthreads();
    if (tid == 0) {
        asm volatile("mbarrier.arrive.expect_tx.shared.b64 _, [%0], %1;"
                     :: "r"(mb), "r"(16 * KDIM * 4) : "memory");
        asm volatile("cp.async.bulk.shared::cluster.global.mbarrier::complete_tx::bytes "
                     "[%0], [%1], %2, [%3];"
                     :: "r"(smem_u32(smS)),
                        "l"(sites + (size_t)b * (16 * KDIM)),
                        "r"(16 * KDIM * 4), "r"(mb)
                     : "memory");
    }
    // All threads wait for the bulk copy (phase 0).
    {
        uint32_t done;
        asm volatile(
            "{\n\t.reg .pred p;\n\t"
            "mbarrier.try_wait.parity.acquire.cta.shared::cta.b64 p, [%1], %2;\n\t"
            "selp.b32 %0, 1, 0, p;\n\t}"
            : "=r"(done) : "r"(mb), "r"(0) : "memory");
        if (!done) {
            asm volatile(
                "{\n\t.reg .pred P1;\n\t"
                "W_%=:\n\t"
                "mbarrier.try_wait.parity.acquire.cta.shared::cta.b64 P1, [%0], %1, 0x989680;\n\t"
                "@P1 bra.uni D_%=;\n\t"
                "bra.uni W_%=;\n\t"
                "D_%=:\n\t}"
                :: "r"(mb), "r"(0) : "memory");
        }
    }

    // Row r = 256 floats = 64 x 16B. Lane owns chunks (lane) and (lane+32).
    const ulonglong2* S2 = (const ulonglong2*)smS;

    if (warp < 2) {
        // M8 rows i = warp*4..warp*4+3 vs rows 8..15 -> 32 outputs
        ulonglong2 Ar[4][2];
        #pragma unroll
        for (int a = 0; a < 4; a++) {
            Ar[a][0] = S2[(warp * 4 + a) * 64 + lane];
            Ar[a][1] = S2[(warp * 4 + a) * 64 + lane + 32];
        }
        float v[32];
        #pragma unroll
        for (int j = 0; j < 8; j++) {
            ulonglong2 B0 = S2[(8 + j) * 64 + lane];
            ulonglong2 B1 = S2[(8 + j) * 64 + lane + 32];
            #pragma unroll
            for (int a = 0; a < 4; a++) {
                unsigned long long d;
                MUL_F32X2(d, Ar[a][0].x, B0.x);
                FMA_F32X2(d, Ar[a][0].y, B0.y, d);
                FMA_F32X2(d, Ar[a][1].x, B1.x, d);
                FMA_F32X2(d, Ar[a][1].y, B1.y, d);
                float lo, hi; UNPACK_F32X2(lo, hi, d);
                v[a * 8 + j] = lo + hi;
            }
        }
        // Multi-value tree reduce: lane l ends with output l in v[0].
        #pragma unroll
        for (int stride = 16; stride >= 1; stride >>= 1) {
            #pragma unroll
            for (int j = 0; j < stride; j++) {
                float send = (lane & stride) ? v[j] : v[j + stride];
                float recv = __shfl_xor_sync(0xffffffffu, send, stride);
                v[j] = ((lane & stride) ? v[j + stride] : v[j]) + recv;
            }
        }
        g_scratch[b * 96 + warp * 32 + lane] = v[0];
    } else {
        // warp2: ML (rows 0-3 x 4-7); warp3: MR (rows 8-11 x 12-15) -> 16 outputs
        const int ra   = (warp == 2) ? 0 : 8;
        const int base = (warp == 2) ? 64 : 80;
        ulonglong2 Ar[4][2];
        #pragma unroll
        for (int a = 0; a < 4; a++) {
            Ar[a][0] = S2[(ra + a) * 64 + lane];
            Ar[a][1] = S2[(ra + a) * 64 + lane + 32];
        }
        float v[16];
        #pragma unroll
        for (int j = 0; j < 4; j++) {
            ulonglong2 B0 = S2[(ra + 4 + j) * 64 + lane];
            ulonglong2 B1 = S2[(ra + 4 + j) * 64 + lane + 32];
            #pragma unroll
            for (int a = 0; a < 4; a++) {
                unsigned long long d;
                MUL_F32X2(d, Ar[a][0].x, B0.x);
                FMA_F32X2(d, Ar[a][0].y, B0.y, d);
                FMA_F32X2(d, Ar[a][1].x, B1.x, d);
                FMA_F32X2(d, Ar[a][1].y, B1.y, d);
                float lo, hi; UNPACK_F32X2(lo, hi, d);
                v[a * 4 + j] = lo + hi;
            }
        }
        #pragma unroll
        for (int j = 0; j < 16; j++) v[j] += __shfl_xor_sync(0xffffffffu, v[j], 16);
        #pragma unroll
        for (int stride = 8; stride >= 1; stride >>= 1) {
            #pragma unroll
            for (int j = 0; j < stride; j++) {
                float send = (lane & stride) ? v[j] : v[j + stride];
                float recv = __shfl_xor_sync(0xffffffffu, send, stride);
                v[j] = ((lane & stride) ? v[j + stride] : v[j]) + recv;
            }
        }
        if (lane < 16) g_scratch[b * 96 + base + lane] = v[0];
    }
}

// ---------------------------------------------------------------------------
// Kernel 2: 8 lanes per element (one column per lane, one-sided Jacobi),
// incremental column norms, merged 8x8/4x4 sweeps. Block=32, grid=2048
// (R15 best: 12.70us).
// ---------------------------------------------------------------------------
#define ROUND8(r) do {                                                        \
    const int partner = prt8[r];                                              \
    float bc[8];                                                              \
    _Pragma("unroll")                                                         \
    for (int k = 0; k < 8; k++) bc[k] = __shfl_sync(FULL, a[k], partner, 8);  \
    float bn = __shfl_sync(FULL, n8, partner, 8);                             \
    float g0 = 0.f, g1 = 0.f;                                                 \
    _Pragma("unroll")                                                         \
    for (int k = 0; k < 4; k++) g0 = fmaf(a[k], bc[k], g0);                   \
    _Pragma("unroll")                                                         \
    for (int k = 4; k < 8; k++) g1 = fmaf(a[k], bc[k], g1);                   \
    float ga = g0 + g1;                                                       \
    float d = bn - n8;                                                        \
    float den = fabsf(d) + sqrtf(fmaf(d, d, 4.f * ga * ga));                  \
    float t = (2.f * ga * copysignf(1.f, d)) * __fdividef(1.f, den);          \
    t = (fabsf(ga) > 1e-30f) ? t : 0.f;                                       \
    float c = rsqrtf(fmaf(t, t, 1.f));                                        \
    float s = c * t;                                                          \
    _Pragma("unroll")                                                         \
    for (int k = 0; k < 8; k++) a[k] = fmaf(c, a[k], -s * bc[k]);             \
    n8 = fmaf(c * c, n8, fmaf(s * s, bn, -2.f * c * s * ga));                 \
} while (0)

#define ROUND4(r) do {                                                        \
    const int partner = prt4[r];                                              \
    float bc[4];                                                              \
    _Pragma("unroll")                                                         \
    for (int k = 0; k < 4; k++) bc[k] = __shfl_sync(FULL, m4[k], partner, 4); \
    float bn = __shfl_sync(FULL, n4, partner, 4);                             \
    float g0 = fmaf(m4[0], bc[0], 0.f); g0 = fmaf(m4[1], bc[1], g0);          \
    float g1 = fmaf(m4[2], bc[2], 0.f); g1 = fmaf(m4[3], bc[3], g1);          \
    float ga = g0 + g1;                                                       \
    float d = bn - n4;                                                        \
    float den = fabsf(d) + sqrtf(fmaf(d, d, 4.f * ga * ga));                  \
    float t = (2.f * ga * copysignf(1.f, d)) * __fdividef(1.f, den);          \
    t = (fabsf(ga) > 1e-30f) ? t : 0.f;                                       \
    float c = rsqrtf(fmaf(t, t, 1.f));                                        \
    float s = c * t;                                                          \
    _Pragma("unroll")                                                         \
    for (int k = 0; k < 4; k++) m4[k] = fmaf(c, m4[k], -s * bc[k]);           \
    n4 = fmaf(c * c, n4, fmaf(s * s, bn, -2.f * c * s * ga));                 \
} while (0)

__global__ __launch_bounds__(32)
void jacobi_kernel(float* __restrict__ out) {
    const unsigned FULL = 0xffffffffu;
    const int tid = threadIdx.x;
    const int j   = tid & 7;                       // my column (8x8)
    const int b   = blockIdx.x * 4 + (tid >> 3);   // element
    const float* base = g_scratch + b * 96;

    float a[8];
    #pragma unroll
    for (int k = 0; k < 8; k++) a[k] = base[k * 8 + j];

    const int j4  = j & 3;
    const int isR = j >> 2;                        // lanes 0-3 -> ML, 4-7 -> MR
    const float* mb = base + 64 + isR * 16;
    float m4[4];
    #pragma unroll
    for (int k = 0; k < 4; k++) m4[k] = mb[k * 4 + j4];

    int prt8[7];
    #pragma unroll
    for (int r = 0; r < 7; r++)
        prt8[r] = (j == r) ? 7 : ((j == 7) ? r : ((2 * r + 14 - j) % 7));
    int prt4[3];
    #pragma unroll
    for (int r = 0; r < 3; r++)
        prt4[r] = (j4 == r) ? 3 : ((j4 == 3) ? r : ((2 * r + 6 - j4) % 3));

    // Initial norms; thereafter updated incrementally per rotation.
    float n8;
    {
        float n0 = 0.f, n1 = 0.f;
        #pragma unroll
        for (int k = 0; k < 4; k++) n0 = fmaf(a[k], a[k], n0);
        #pragma unroll
        for (int k = 4; k < 8; k++) n1 = fmaf(a[k], a[k], n1);
        n8 = n0 + n1;
    }
    float n4;
    {
        float n0 = fmaf(m4[0], m4[0], 0.f); n0 = fmaf(m4[1], m4[1], n0);
        float n1 = fmaf(m4[2], m4[2], 0.f); n1 = fmaf(m4[3], m4[3], n1);
        n4 = n0 + n1;
    }

    // 3 merged sweeps: 7 rounds of 8x8; rounds 0-2 carry a 4x4 round too.
    #pragma unroll 1
    for (int sw = 0; sw < 3; sw++) {
        #pragma unroll
        for (int r = 0; r < 7; r++) {
            ROUND8(r);
            if (r < 3) ROUND4(r);
        }
    }
    // Final 8x8-only sweep (4 sweeps total for 8x8, 3 for 4x4).
    #pragma unroll
    for (int r = 0; r < 7; r++) ROUND8(r);

    // ---- entropies (norms recomputed exactly) ----
    float sq8 = EPSF;
    #pragma unroll
    for (int k = 0; k < 8; k++) sq8 = fmaf(a[k], a[k], sq8);
    float T8 = sq8;
    #pragma unroll
    for (int m = 4; m >= 1; m >>= 1) T8 += __shfl_xor_sync(FULL, T8, m, 8);
    float p8 = sq8 * __fdividef(1.f, T8);
    float s8 = p8 * __logf(p8 + EPSF);
    #pragma unroll
    for (int m = 4; m >= 1; m >>= 1) s8 += __shfl_xor_sync(FULL, s8, m, 8);

    float sq4 = EPSF;
    #pragma unroll
    for (int k = 0; k < 4; k++) sq4 = fmaf(m4[k], m4[k], sq4);
    float T4 = sq4;
    #pragma unroll
    for (int m = 2; m >= 1; m >>= 1) T4 += __shfl_xor_sync(FULL, T4, m, 4);
    float p4 = sq4 * __fdividef(1.f, T4);
    float s4 = p4 * __logf(p4 + EPSF);
    #pragma unroll
    for (int m = 2; m >= 1; m >>= 1) s4 += __shfl_xor_sync(FULL, s4, m, 4);

    float s4R = __shfl_sync(FULL, s4, 4, 8);   // MR sum from lane 4 of group
    if (j == 0) {
        // phi = S_whole - S_left - S_right = -s8 + s4(L) + s4(R)
        float phi = -s8 + s4 + s4R;
        out[b] = phi > 0.f ? phi : 0.f;
    }
}

extern "C" void kernel_launch(void* const* d_in, const int* in_sizes, int n_in,
                              void* d_out, int out_size) {
    const float* sites = (const float*)d_in[0];
    float* out = (float*)d_out;
    gram_kernel<<<BATCH, 128>>>(sites);
    jacobi_kernel<<<BATCH / 4, 32>>>(out);
}